// round 12
// baseline (speedup 1.0000x reference)
#include <cuda_runtime.h>
#include <cuda_fp16.h>
#include <stdint.h>

// PolylineEncoder on fp16 HMMA (mma.sync.f32.f16.f16.f32).
// R12: fp16 replaces bf16. Layer1 = 3-term (x hi/lo x W1 hi/lo) -> h exact to
// 2^-22; h stored as ONE fp16 plane (single 2^-11 rounding); layer2 = 2-term
// (h x W2_hi + h x W2_lo). mma count 216 -> 152 per warp-tile, h smem halved,
// s-loop ldmatrix halved. smem 22.6 KB -> launch_bounds(256,4), 4 CTAs/SM
// (L1D ~137 KB keeps the 72 KB fragment tables resident, unlike R10).

#define NEG_INF_F (-1e9f)
#define NT 256
#define TILE_PTS 64

__device__ __align__(16) uint4 g_bfrag [8 * 16 * 32];   // W2 hi/lo frags, 64 KB
__device__ __align__(16) uint4 g_w1frag[16 * 32];       // W1 hi/lo frags, 8 KB

// smem byte offsets
#define SM_STG   0        // 2 bufs x (2304 x + 256 mask)
#define STG_STRIDE 2560
#define SM_FLG   5120     // 64
#define SM_RED   5184     // 1024
#define SM_HH    6208     // 64*64*4 = 16384 (single fp16 h plane)
#define SM_BYTES 22592

// h-plane word index (row p 0..63, word w 0..63), 4-word rotation: 16B blocks
// contiguous (ldmatrix-compatible); conflict-free for epi-1 STS.32 and
// ldmatrix read phases.
__device__ __forceinline__ uint32_t hword(int p, int w) {
    return (uint32_t)(p * 64 + ((w + 4 * (p & 7)) & 63));
}

__device__ __forceinline__ void ldm4(uint32_t r[4], uint32_t addr) {
    asm volatile("ldmatrix.sync.aligned.m8n8.x4.shared.b16 {%0,%1,%2,%3}, [%4];"
                 : "=r"(r[0]), "=r"(r[1]), "=r"(r[2]), "=r"(r[3]) : "r"(addr));
}

__device__ __forceinline__ void mma16816(float acc[4], const uint32_t a[4],
                                         uint32_t b0, uint32_t b1) {
    asm volatile("mma.sync.aligned.m16n8k16.row.col.f32.f16.f16.f32 "
                 "{%0,%1,%2,%3}, {%4,%5,%6,%7}, {%8,%9}, {%0,%1,%2,%3};"
                 : "+f"(acc[0]), "+f"(acc[1]), "+f"(acc[2]), "+f"(acc[3])
                 : "r"(a[0]), "r"(a[1]), "r"(a[2]), "r"(a[3]), "r"(b0), "r"(b1));
}

__device__ __forceinline__ uint32_t hpack(float a, float b) {
    const __half2 h = __floats2half2_rn(a, b);
    return *(const uint32_t*)&h;
}

// fp16 hi/lo split of a float pair
__device__ __forceinline__ uint32_t hsplit(float v0, float v1, uint32_t& lo) {
    const __half h0 = __float2half_rn(v0), h1 = __float2half_rn(v1);
    lo = hpack(v0 - __half2float(h0), v1 - __half2float(h1));
    const __half2 hh = __halves2half2(h0, h1);
    return *(const uint32_t*)&hh;
}

__device__ __forceinline__ uint32_t wpair(const float* W, int k, int n,
                                          uint32_t& lo, int kmax) {
    const float v0 = (k < kmax)     ? W[k * 128 + n]       : 0.0f;
    const float v1 = (k + 1 < kmax) ? W[(k + 1) * 128 + n] : 0.0f;
    return hsplit(v0, v1, lo);
}

__device__ __forceinline__ void cp16(uint32_t dst, const void* src) {
    asm volatile("cp.async.cg.shared.global [%0], [%1], 16;" :: "r"(dst), "l"(src));
}
#define CP_COMMIT() asm volatile("cp.async.commit_group;" ::: "memory")
#define CP_WAIT1()  asm volatile("cp.async.wait_group 1;" ::: "memory")

// ---- prep: W2 and W1 -> mma B fragments (col-major), fp16 hi+lo ----
__global__ void prep_kernel(const float* __restrict__ W1, const float* __restrict__ W2) {
    const int idx = blockIdx.x * blockDim.x + threadIdx.x;
    if (idx < 8 * 16 * 32) {
        const int lane = idx & 31, nf = (idx >> 5) & 15, s = idx >> 9;
        const int k0 = s * 16 + 2 * (lane & 3);
        const int n  = nf * 8 + (lane >> 2);
        uint32_t l0, l1;
        const uint32_t h0 = wpair(W2, k0,     n, l0, 128);
        const uint32_t h1 = wpair(W2, k0 + 8, n, l1, 128);
        g_bfrag[idx] = make_uint4(h0, h1, l0, l1);
    }
    if (idx < 16 * 32) {
        const int lane = idx & 31, nf = idx >> 5;
        const int k0 = 2 * (lane & 3);
        const int n  = nf * 8 + (lane >> 2);
        uint32_t l0, l1;
        const uint32_t h0 = wpair(W1, k0,     n, l0, 9);
        const uint32_t h1 = wpair(W1, k0 + 8, n, l1, 9);
        g_w1frag[idx] = make_uint4(h0, h1, l0, l1);
    }
}

extern __shared__ unsigned char smB[];

__device__ __forceinline__ void stage_tile(uint32_t sb, int buf,
                                           const float* poly, const int* mask,
                                           int tile, int tid) {
    const uint32_t dst = sb + SM_STG + (uint32_t)buf * STG_STRIDE;
    if (tid < 144)
        cp16(dst + tid * 16, (const char*)poly + (size_t)tile * 2304 + tid * 16);
    else if (tid < 160)
        cp16(dst + 2304 + (tid - 144) * 16,
             (const char*)mask + (size_t)tile * 256 + (tid - 144) * 16);
}

__global__ void __launch_bounds__(NT, 4)
poly_mma_kernel(const float* __restrict__ poly, const int* __restrict__ mask,
                const float* __restrict__ b1g, const float* __restrict__ b2g,
                float* __restrict__ out, int ntiles)
{
    const int tid = threadIdx.x, wid = tid >> 5, lane = tid & 31;
    uint32_t* flgs = (uint32_t*)(smB + SM_FLG);
    float* red = (float*)(smB + SM_RED);

    uint32_t sb;
    asm("{ .reg .u64 t; cvta.to.shared.u64 t, %1; cvt.u32.u64 %0, t; }"
        : "=r"(sb) : "l"(smB));

    const int lr = lane >> 2, lc = lane & 3;    // fragment lane coords
    const int mq = wid & 1, nq = wid >> 1;      // warp = (M-quad, N-quarter)
    const int mbase = 32 * mq;

    // per-thread b1 pairs
    float b1r[8];
    #pragma unroll
    for (int nf = 0; nf < 4; ++nf) {
        b1r[2 * nf]     = b1g[nq * 32 + nf * 8 + 2 * lc];
        b1r[2 * nf + 1] = b1g[nq * 32 + nf * 8 + 2 * lc + 1];
    }

    // ldmatrix lane-address components
    const int lsub = lane >> 3;
    const int lrow = (lsub & 1) * 8 + (lane & 7);
    const int lkb  = (lsub >> 1) * 4;

    // prologue: prefetch first tile into buf 0
    int buf = 0;
    if (blockIdx.x < ntiles) stage_tile(sb, 0, poly, mask, blockIdx.x, tid);
    CP_COMMIT();

    for (int tile = blockIdx.x; tile < ntiles; tile += gridDim.x) {
        const int tn = tile + gridDim.x;
        stage_tile(sb, buf ^ 1, poly, mask, (tn < ntiles) ? tn : tile, tid);
        CP_COMMIT();
        CP_WAIT1();
        __syncthreads();       // bar #1

        const float* xs = (const float*)(smB + SM_STG + (uint32_t)buf * STG_STRIDE);
        const int* msks = (const int*)(smB + SM_STG + (uint32_t)buf * STG_STRIDE + 2304);

        if (tid < TILE_PTS) {
            const uint32_t bal = __ballot_sync(0xffffffffu, msks[tid] != 0);
            if (lane == 0) flgs[wid] = bal;
        }

        float acc[2][4][4];

        // ---- MMA1: h = x @ W1 (K=16, 3-term fp16); A built in registers ----
        {
            uint32_t xah[2][4], xal[2][4];
            #pragma unroll
            for (int mi = 0; mi < 2; ++mi) {
                const int rA = mbase + 16 * mi + lr, rB = rA + 8;
                xah[mi][0] = hsplit(xs[rA * 9 + 2 * lc], xs[rA * 9 + 2 * lc + 1], xal[mi][0]);
                xah[mi][1] = hsplit(xs[rB * 9 + 2 * lc], xs[rB * 9 + 2 * lc + 1], xal[mi][1]);
                if (lc == 0) {
                    xah[mi][2] = hsplit(xs[rA * 9 + 8], 0.0f, xal[mi][2]);
                    xah[mi][3] = hsplit(xs[rB * 9 + 8], 0.0f, xal[mi][3]);
                } else {
                    xah[mi][2] = 0; xah[mi][3] = 0; xal[mi][2] = 0; xal[mi][3] = 0;
                }
            }
            #pragma unroll
            for (int mi = 0; mi < 2; ++mi)
                #pragma unroll
                for (int nf = 0; nf < 4; ++nf)
                    #pragma unroll
                    for (int e = 0; e < 4; ++e) acc[mi][nf][e] = 0.0f;
            #pragma unroll
            for (int nf = 0; nf < 4; ++nf) {
                const uint4 B = __ldg(&g_w1frag[(nq * 4 + nf) * 32 + lane]);
                #pragma unroll
                for (int mi = 0; mi < 2; ++mi) {
                    mma16816(acc[mi][nf], xah[mi], B.x, B.y);   // xh * W1h
                    mma16816(acc[mi][nf], xah[mi], B.z, B.w);   // xh * W1l
                    mma16816(acc[mi][nf], xal[mi], B.x, B.y);   // xl * W1h
                }
            }
            // epilogue-1: +b1, relu, round to fp16 -> single h plane
            #pragma unroll
            for (int nf = 0; nf < 4; ++nf) {
                const int w = nq * 16 + nf * 4 + lc;
                #pragma unroll
                for (int mi = 0; mi < 2; ++mi) {
                    const int r = mbase + 16 * mi + lr;
                    const float e0 = fmaxf(acc[mi][nf][0] + b1r[2 * nf],     0.0f);
                    const float e1 = fmaxf(acc[mi][nf][1] + b1r[2 * nf + 1], 0.0f);
                    const float e2 = fmaxf(acc[mi][nf][2] + b1r[2 * nf],     0.0f);
                    const float e3 = fmaxf(acc[mi][nf][3] + b1r[2 * nf + 1], 0.0f);
                    *(uint32_t*)(smB + SM_HH + 4 * hword(r, w))     = hpack(e0, e1);
                    *(uint32_t*)(smB + SM_HH + 4 * hword(r + 8, w)) = hpack(e2, e3);
                }
            }
        }
        __syncthreads();       // bar #2

        // ---- MMA2: feat = h @ W2 (K=128, 2-term fp16) ----
        #pragma unroll
        for (int mi = 0; mi < 2; ++mi)
            #pragma unroll
            for (int nf = 0; nf < 4; ++nf)
                #pragma unroll
                for (int e = 0; e < 4; ++e) acc[mi][nf][e] = 0.0f;

        #pragma unroll 1
        for (int s = 0; s < 8; ++s) {
            uint32_t ah[2][4];
            const int w0 = 8 * s + lkb;
            #pragma unroll
            for (int mi = 0; mi < 2; ++mi)
                ldm4(ah[mi], sb + SM_HH + 4 * hword(mbase + 16 * mi + lrow, w0));
            #pragma unroll
            for (int nf = 0; nf < 4; ++nf) {
                const uint4 B = __ldg(&g_bfrag[(s * 16 + nq * 4 + nf) * 32 + lane]);
                #pragma unroll
                for (int mi = 0; mi < 2; ++mi) {
                    mma16816(acc[mi][nf], ah[mi], B.x, B.y);   // h * W2h
                    mma16816(acc[mi][nf], ah[mi], B.z, B.w);   // h * W2l
                }
            }
        }

        // ---- epilogue-2: masked max over the warp's 32 points ----
        const int m00 = msks[mbase + lr] != 0,      m01 = msks[mbase + lr + 8] != 0;
        const int m10 = msks[mbase + 16 + lr] != 0, m11 = msks[mbase + 24 + lr] != 0;
        #pragma unroll
        for (int nf = 0; nf < 4; ++nf) {
            float e0 = NEG_INF_F, e1 = NEG_INF_F;
            if (m00) { e0 = fmaxf(e0, acc[0][nf][0]); e1 = fmaxf(e1, acc[0][nf][1]); }
            if (m01) { e0 = fmaxf(e0, acc[0][nf][2]); e1 = fmaxf(e1, acc[0][nf][3]); }
            if (m10) { e0 = fmaxf(e0, acc[1][nf][0]); e1 = fmaxf(e1, acc[1][nf][1]); }
            if (m11) { e0 = fmaxf(e0, acc[1][nf][2]); e1 = fmaxf(e1, acc[1][nf][3]); }
            #pragma unroll
            for (int off = 4; off < 32; off <<= 1) {
                e0 = fmaxf(e0, __shfl_xor_sync(0xffffffffu, e0, off));
                e1 = fmaxf(e1, __shfl_xor_sync(0xffffffffu, e1, off));
            }
            if (lane < 4) {
                const int n = nq * 32 + nf * 8 + 2 * lane;
                red[mq * 128 + n]     = e0;
                red[mq * 128 + n + 1] = e1;
            }
        }
        __syncthreads();       // bar #3

        // ---- final: combine 2 M-quads, +b2, any-valid (1 polyline/tile) ----
        if (tid < 128) {
            const float v = fmaxf(red[tid], red[128 + tid]);
            const uint32_t av = flgs[0] | flgs[1];
            out[(size_t)tile * 128 + tid] = av ? v + __ldg(&b2g[tid]) : 0.0f;
        }

        buf ^= 1;
    }
}

extern "C" void kernel_launch(void* const* d_in, const int* in_sizes, int n_in,
                              void* d_out, int out_size)
{
    const float* poly = (const float*)d_in[0];
    const int*   mask = (const int*)  d_in[1];
    const float* W1   = (const float*)d_in[2];
    const float* b1   = (const float*)d_in[3];
    const float* W2   = (const float*)d_in[4];
    const float* b2   = (const float*)d_in[5];
    float* out = (float*)d_out;

    const int npoints = in_sizes[0] / 9;           // 1,048,576
    const int ntiles  = npoints / TILE_PTS;        // 16384

    prep_kernel<<<16, 256>>>(W1, W2);

    cudaFuncSetAttribute(poly_mma_kernel,
                         cudaFuncAttributeMaxDynamicSharedMemorySize, SM_BYTES);
    poly_mma_kernel<<<592, NT, SM_BYTES>>>(poly, mask, b1, b2, out, ntiles);
}

// round 13
// speedup vs baseline: 1.5883x; 1.5883x over previous
#include <cuda_runtime.h>
#include <cuda_fp16.h>
#include <stdint.h>

// PolylineEncoder on fp16 HMMA (mma.sync.f32.f16.f16.f32).
// R13: R12's fp16 math (L1 3-term, h single fp16 plane, L2 2-term; 152 mma vs
// bf16's 216) with the occupancy reverted to 3 CTAs/SM — R10/R12 showed the
// 4-CTA config costs ~60-80us (barrier/issue contention at 32 warps) even
// when the L1-resident fragment tables survive.

#define NEG_INF_F (-1e9f)
#define NT 256
#define TILE_PTS 64

__device__ __align__(16) uint4 g_bfrag [8 * 16 * 32];   // W2 hi/lo frags, 64 KB
__device__ __align__(16) uint4 g_w1frag[16 * 32];       // W1 hi/lo frags, 8 KB

// smem byte offsets
#define SM_STG   0        // 2 bufs x (2304 x + 256 mask)
#define STG_STRIDE 2560
#define SM_FLG   5120     // 64
#define SM_RED   5184     // 1024
#define SM_HH    6208     // 64*64*4 = 16384 (single fp16 h plane)
#define SM_BYTES 22592

// h-plane word index (row p 0..63, word w 0..63), 4-word rotation: 16B blocks
// contiguous (ldmatrix-compatible); conflict-free for epi-1 STS.32 and
// ldmatrix read phases.
__device__ __forceinline__ uint32_t hword(int p, int w) {
    return (uint32_t)(p * 64 + ((w + 4 * (p & 7)) & 63));
}

__device__ __forceinline__ void ldm4(uint32_t r[4], uint32_t addr) {
    asm volatile("ldmatrix.sync.aligned.m8n8.x4.shared.b16 {%0,%1,%2,%3}, [%4];"
                 : "=r"(r[0]), "=r"(r[1]), "=r"(r[2]), "=r"(r[3]) : "r"(addr));
}

__device__ __forceinline__ void mma16816(float acc[4], const uint32_t a[4],
                                         uint32_t b0, uint32_t b1) {
    asm volatile("mma.sync.aligned.m16n8k16.row.col.f32.f16.f16.f32 "
                 "{%0,%1,%2,%3}, {%4,%5,%6,%7}, {%8,%9}, {%0,%1,%2,%3};"
                 : "+f"(acc[0]), "+f"(acc[1]), "+f"(acc[2]), "+f"(acc[3])
                 : "r"(a[0]), "r"(a[1]), "r"(a[2]), "r"(a[3]), "r"(b0), "r"(b1));
}

__device__ __forceinline__ uint32_t hpack(float a, float b) {
    const __half2 h = __floats2half2_rn(a, b);
    return *(const uint32_t*)&h;
}

// fp16 hi/lo split of a float pair
__device__ __forceinline__ uint32_t hsplit(float v0, float v1, uint32_t& lo) {
    const __half h0 = __float2half_rn(v0), h1 = __float2half_rn(v1);
    lo = hpack(v0 - __half2float(h0), v1 - __half2float(h1));
    const __half2 hh = __halves2half2(h0, h1);
    return *(const uint32_t*)&hh;
}

__device__ __forceinline__ uint32_t wpair(const float* W, int k, int n,
                                          uint32_t& lo, int kmax) {
    const float v0 = (k < kmax)     ? W[k * 128 + n]       : 0.0f;
    const float v1 = (k + 1 < kmax) ? W[(k + 1) * 128 + n] : 0.0f;
    return hsplit(v0, v1, lo);
}

__device__ __forceinline__ void cp16(uint32_t dst, const void* src) {
    asm volatile("cp.async.cg.shared.global [%0], [%1], 16;" :: "r"(dst), "l"(src));
}
#define CP_COMMIT() asm volatile("cp.async.commit_group;" ::: "memory")
#define CP_WAIT1()  asm volatile("cp.async.wait_group 1;" ::: "memory")

// ---- prep: W2 and W1 -> mma B fragments (col-major), fp16 hi+lo ----
__global__ void prep_kernel(const float* __restrict__ W1, const float* __restrict__ W2) {
    const int idx = blockIdx.x * blockDim.x + threadIdx.x;
    if (idx < 8 * 16 * 32) {
        const int lane = idx & 31, nf = (idx >> 5) & 15, s = idx >> 9;
        const int k0 = s * 16 + 2 * (lane & 3);
        const int n  = nf * 8 + (lane >> 2);
        uint32_t l0, l1;
        const uint32_t h0 = wpair(W2, k0,     n, l0, 128);
        const uint32_t h1 = wpair(W2, k0 + 8, n, l1, 128);
        g_bfrag[idx] = make_uint4(h0, h1, l0, l1);
    }
    if (idx < 16 * 32) {
        const int lane = idx & 31, nf = idx >> 5;
        const int k0 = 2 * (lane & 3);
        const int n  = nf * 8 + (lane >> 2);
        uint32_t l0, l1;
        const uint32_t h0 = wpair(W1, k0,     n, l0, 9);
        const uint32_t h1 = wpair(W1, k0 + 8, n, l1, 9);
        g_w1frag[idx] = make_uint4(h0, h1, l0, l1);
    }
}

extern __shared__ unsigned char smB[];

__device__ __forceinline__ void stage_tile(uint32_t sb, int buf,
                                           const float* poly, const int* mask,
                                           int tile, int tid) {
    const uint32_t dst = sb + SM_STG + (uint32_t)buf * STG_STRIDE;
    if (tid < 144)
        cp16(dst + tid * 16, (const char*)poly + (size_t)tile * 2304 + tid * 16);
    else if (tid < 160)
        cp16(dst + 2304 + (tid - 144) * 16,
             (const char*)mask + (size_t)tile * 256 + (tid - 144) * 16);
}

__global__ void __launch_bounds__(NT, 3)
poly_mma_kernel(const float* __restrict__ poly, const int* __restrict__ mask,
                const float* __restrict__ b1g, const float* __restrict__ b2g,
                float* __restrict__ out, int ntiles)
{
    const int tid = threadIdx.x, wid = tid >> 5, lane = tid & 31;
    uint32_t* flgs = (uint32_t*)(smB + SM_FLG);
    float* red = (float*)(smB + SM_RED);

    uint32_t sb;
    asm("{ .reg .u64 t; cvta.to.shared.u64 t, %1; cvt.u32.u64 %0, t; }"
        : "=r"(sb) : "l"(smB));

    const int lr = lane >> 2, lc = lane & 3;    // fragment lane coords
    const int mq = wid & 1, nq = wid >> 1;      // warp = (M-quad, N-quarter)
    const int mbase = 32 * mq;

    // per-thread b1 pairs
    float b1r[8];
    #pragma unroll
    for (int nf = 0; nf < 4; ++nf) {
        b1r[2 * nf]     = b1g[nq * 32 + nf * 8 + 2 * lc];
        b1r[2 * nf + 1] = b1g[nq * 32 + nf * 8 + 2 * lc + 1];
    }

    // ldmatrix lane-address components
    const int lsub = lane >> 3;
    const int lrow = (lsub & 1) * 8 + (lane & 7);
    const int lkb  = (lsub >> 1) * 4;

    // prologue: prefetch first tile into buf 0
    int buf = 0;
    if (blockIdx.x < ntiles) stage_tile(sb, 0, poly, mask, blockIdx.x, tid);
    CP_COMMIT();

    for (int tile = blockIdx.x; tile < ntiles; tile += gridDim.x) {
        const int tn = tile + gridDim.x;
        stage_tile(sb, buf ^ 1, poly, mask, (tn < ntiles) ? tn : tile, tid);
        CP_COMMIT();
        CP_WAIT1();
        __syncthreads();       // bar #1

        const float* xs = (const float*)(smB + SM_STG + (uint32_t)buf * STG_STRIDE);
        const int* msks = (const int*)(smB + SM_STG + (uint32_t)buf * STG_STRIDE + 2304);

        if (tid < TILE_PTS) {
            const uint32_t bal = __ballot_sync(0xffffffffu, msks[tid] != 0);
            if (lane == 0) flgs[wid] = bal;
        }

        float acc[2][4][4];

        // ---- MMA1: h = x @ W1 (K=16, 3-term fp16); A built in registers ----
        {
            uint32_t xah[2][4], xal[2][4];
            #pragma unroll
            for (int mi = 0; mi < 2; ++mi) {
                const int rA = mbase + 16 * mi + lr, rB = rA + 8;
                xah[mi][0] = hsplit(xs[rA * 9 + 2 * lc], xs[rA * 9 + 2 * lc + 1], xal[mi][0]);
                xah[mi][1] = hsplit(xs[rB * 9 + 2 * lc], xs[rB * 9 + 2 * lc + 1], xal[mi][1]);
                if (lc == 0) {
                    xah[mi][2] = hsplit(xs[rA * 9 + 8], 0.0f, xal[mi][2]);
                    xah[mi][3] = hsplit(xs[rB * 9 + 8], 0.0f, xal[mi][3]);
                } else {
                    xah[mi][2] = 0; xah[mi][3] = 0; xal[mi][2] = 0; xal[mi][3] = 0;
                }
            }
            #pragma unroll
            for (int mi = 0; mi < 2; ++mi)
                #pragma unroll
                for (int nf = 0; nf < 4; ++nf)
                    #pragma unroll
                    for (int e = 0; e < 4; ++e) acc[mi][nf][e] = 0.0f;
            #pragma unroll
            for (int nf = 0; nf < 4; ++nf) {
                const uint4 B = __ldg(&g_w1frag[(nq * 4 + nf) * 32 + lane]);
                #pragma unroll
                for (int mi = 0; mi < 2; ++mi) {
                    mma16816(acc[mi][nf], xah[mi], B.x, B.y);   // xh * W1h
                    mma16816(acc[mi][nf], xah[mi], B.z, B.w);   // xh * W1l
                    mma16816(acc[mi][nf], xal[mi], B.x, B.y);   // xl * W1h
                }
            }
            // epilogue-1: +b1, relu, round to fp16 -> single h plane
            #pragma unroll
            for (int nf = 0; nf < 4; ++nf) {
                const int w = nq * 16 + nf * 4 + lc;
                #pragma unroll
                for (int mi = 0; mi < 2; ++mi) {
                    const int r = mbase + 16 * mi + lr;
                    const float e0 = fmaxf(acc[mi][nf][0] + b1r[2 * nf],     0.0f);
                    const float e1 = fmaxf(acc[mi][nf][1] + b1r[2 * nf + 1], 0.0f);
                    const float e2 = fmaxf(acc[mi][nf][2] + b1r[2 * nf],     0.0f);
                    const float e3 = fmaxf(acc[mi][nf][3] + b1r[2 * nf + 1], 0.0f);
                    *(uint32_t*)(smB + SM_HH + 4 * hword(r, w))     = hpack(e0, e1);
                    *(uint32_t*)(smB + SM_HH + 4 * hword(r + 8, w)) = hpack(e2, e3);
                }
            }
        }
        __syncthreads();       // bar #2

        // ---- MMA2: feat = h @ W2 (K=128, 2-term fp16) ----
        #pragma unroll
        for (int mi = 0; mi < 2; ++mi)
            #pragma unroll
            for (int nf = 0; nf < 4; ++nf)
                #pragma unroll
                for (int e = 0; e < 4; ++e) acc[mi][nf][e] = 0.0f;

        #pragma unroll 1
        for (int s = 0; s < 8; ++s) {
            uint32_t ah[2][4];
            const int w0 = 8 * s + lkb;
            #pragma unroll
            for (int mi = 0; mi < 2; ++mi)
                ldm4(ah[mi], sb + SM_HH + 4 * hword(mbase + 16 * mi + lrow, w0));
            #pragma unroll
            for (int nf = 0; nf < 4; ++nf) {
                const uint4 B = __ldg(&g_bfrag[(s * 16 + nq * 4 + nf) * 32 + lane]);
                #pragma unroll
                for (int mi = 0; mi < 2; ++mi) {
                    mma16816(acc[mi][nf], ah[mi], B.x, B.y);   // h * W2h
                    mma16816(acc[mi][nf], ah[mi], B.z, B.w);   // h * W2l
                }
            }
        }

        // ---- epilogue-2: masked max over the warp's 32 points ----
        const int m00 = msks[mbase + lr] != 0,      m01 = msks[mbase + lr + 8] != 0;
        const int m10 = msks[mbase + 16 + lr] != 0, m11 = msks[mbase + 24 + lr] != 0;
        #pragma unroll
        for (int nf = 0; nf < 4; ++nf) {
            float e0 = NEG_INF_F, e1 = NEG_INF_F;
            if (m00) { e0 = fmaxf(e0, acc[0][nf][0]); e1 = fmaxf(e1, acc[0][nf][1]); }
            if (m01) { e0 = fmaxf(e0, acc[0][nf][2]); e1 = fmaxf(e1, acc[0][nf][3]); }
            if (m10) { e0 = fmaxf(e0, acc[1][nf][0]); e1 = fmaxf(e1, acc[1][nf][1]); }
            if (m11) { e0 = fmaxf(e0, acc[1][nf][2]); e1 = fmaxf(e1, acc[1][nf][3]); }
            #pragma unroll
            for (int off = 4; off < 32; off <<= 1) {
                e0 = fmaxf(e0, __shfl_xor_sync(0xffffffffu, e0, off));
                e1 = fmaxf(e1, __shfl_xor_sync(0xffffffffu, e1, off));
            }
            if (lane < 4) {
                const int n = nq * 32 + nf * 8 + 2 * lane;
                red[mq * 128 + n]     = e0;
                red[mq * 128 + n + 1] = e1;
            }
        }
        __syncthreads();       // bar #3

        // ---- final: combine 2 M-quads, +b2, any-valid (1 polyline/tile) ----
        if (tid < 128) {
            const float v = fmaxf(red[tid], red[128 + tid]);
            const uint32_t av = flgs[0] | flgs[1];
            out[(size_t)tile * 128 + tid] = av ? v + __ldg(&b2g[tid]) : 0.0f;
        }

        buf ^= 1;
    }
}

extern "C" void kernel_launch(void* const* d_in, const int* in_sizes, int n_in,
                              void* d_out, int out_size)
{
    const float* poly = (const float*)d_in[0];
    const int*   mask = (const int*)  d_in[1];
    const float* W1   = (const float*)d_in[2];
    const float* b1   = (const float*)d_in[3];
    const float* W2   = (const float*)d_in[4];
    const float* b2   = (const float*)d_in[5];
    float* out = (float*)d_out;

    const int npoints = in_sizes[0] / 9;           // 1,048,576
    const int ntiles  = npoints / TILE_PTS;        // 16384

    prep_kernel<<<16, 256>>>(W1, W2);

    cudaFuncSetAttribute(poly_mma_kernel,
                         cudaFuncAttributeMaxDynamicSharedMemorySize, SM_BYTES);
    poly_mma_kernel<<<444, NT, SM_BYTES>>>(poly, mask, b1, b2, out, ntiles);
}